// round 14
// baseline (speedup 1.0000x reference)
#include <cuda_runtime.h>
#include <math.h>

#define T 2048
#define B 64
#define H 512
#define D 256
#define NITER (T + 2)

__device__ float g_xw0R[8][H * B];   // xw0 ring (L2-resident, 1MB)
__device__ float g_h1T[4][H * B];    // rings, slot = t & 3
__device__ float g_h2T[4][H * B];
__device__ float g_zT[4][H * B];
__device__ unsigned g_fine[128 * 32];   // per-block counters: (stage*32+sub)*32, 128B apart
__device__ unsigned g_coarse[8 * 32];   // per-(stage,bhalf) counters for ring guards

__device__ __forceinline__ void lds_v2u64(unsigned addr, unsigned long long& a,
                                          unsigned long long& b) {
    asm volatile("ld.shared.v2.u64 {%0,%1}, [%2];" : "=l"(a), "=l"(b) : "r"(addr));
}
__device__ __forceinline__ void lds_u64(unsigned addr, unsigned long long& a) {
    asm volatile("ld.shared.u64 %0, [%1];" : "=l"(a) : "r"(addr));
}
__device__ __forceinline__ void sts_u64(unsigned addr, unsigned long long v) {
    asm volatile("st.shared.u64 [%0], %1;" :: "r"(addr), "l"(v));
}
#define FMA2(acc, w, h) \
    asm("fma.rn.f32x2 %0, %1, %2, %0;" : "+l"(acc) : "l"(w), "l"(h))
__device__ __forceinline__ unsigned long long add2(unsigned long long a,
                                                   unsigned long long b) {
    unsigned long long d;
    asm("add.rn.f32x2 %0, %1, %2;" : "=l"(d) : "l"(a), "l"(b));
    return d;
}
__device__ __forceinline__ float2 unpack2(unsigned long long v) {
    float2 r;
    asm("mov.b64 {%0,%1}, %2;" : "=f"(r.x), "=f"(r.y) : "l"(v));
    return r;
}
__device__ __forceinline__ float tanh_fast(float v) {
    asm("tanh.approx.f32 %0, %0;" : "+f"(v));
    return v;
}
__device__ __forceinline__ void poll_ge(const unsigned* p, unsigned target) {
    unsigned c;
    do {
        asm volatile("ld.global.acquire.gpu.u32 %0, [%1];" : "=r"(c) : "l"(p) : "memory");
    } while ((int)(c - target) < 0);
}

// ---- zero recurrent state rings AND counters (every launch/replay) ----
__global__ void k_zero() {
    int idx = blockIdx.x * 256 + threadIdx.x;
    if (idx < 4 * H * B) {
        ((float*)g_h1T)[idx] = 0.0f;
        ((float*)g_h2T)[idx] = 0.0f;
    }
    if (blockIdx.x == 1) {
        for (int j = threadIdx.x; j < 128 * 32; j += 256) g_fine[j] = 0u;
        for (int j = threadIdx.x; j < 8 * 32; j += 256) g_coarse[j] = 0u;
    }
}

// ---- persistent dataflow pipeline: per-warp chunk consumption ----
// grp 0 (blk  0- 31): h1[t]=tanh(xw0[t] + Whh0 h1[t-1]),  t=i,   K=512
// grp 1 (blk 32- 63): z[t]=bias1 + Wih1 h1[t],            t=i-1, K=512
// grp 2 (blk 64- 95): h2[t]=tanh(z[t] + Whh1 h2[t-1]),    t=i-2, K=512
// grp 3 (blk 96-127): xw0[t]=bias0 + Wih0 x[t],           t=i,   K=256 (free-runs)
// Warp ks consumes the 32-k chunk produced by exactly one upstream block
// (rowblk=ks, same bhalf): poll + stage + body are fully warp-local.
__global__ void __launch_bounds__(512, 1) k_recur(
    const float* __restrict__ Whh0, const float* __restrict__ Wih1,
    const float* __restrict__ Whh1, const float* __restrict__ Wih0,
    const float* __restrict__ x,
    const float* __restrict__ bih0, const float* __restrict__ bhh0,
    const float* __restrict__ bih1, const float* __restrict__ bhh1)
{
    extern __shared__ char smb[];
    const unsigned HB = 131072u;
    const unsigned XI = 65536u;      // x intermediate tile (stage 3 only)

    int stage = blockIdx.x >> 5;
    int sub = blockIdx.x & 31;
    int rowblk = sub >> 1, bhalf = sub & 1;
    int h0 = rowblk * 32;
    int tid = threadIdx.x;
    int ks = tid >> 5;
    int lane = tid & 31;
    int rg = lane >> 2, bg = lane & 3;

    // counters
    unsigned* fine_own = &g_fine[(stage * 32 + sub) * 32];
    unsigned* coarse_own = &g_coarse[(stage * 2 + bhalf) * 32];
    // warp-chunk producer counter (stages 0,1 read h1; stage 2 reads h2)
    const unsigned* wp = 0;
    if (stage == 0 || stage == 1) wp = &g_fine[(0 * 32 + ks * 2 + bhalf) * 32];
    else if (stage == 2)          wp = &g_fine[(2 * 32 + ks * 2 + bhalf) * 32];
    // ex producer counter (same sub): stage0 <- stage3 (target i+1), stage2 <- stage1 (target i)
    const unsigned* xp = 0;
    if (stage == 0)      xp = &g_fine[(3 * 32 + sub) * 32];
    else if (stage == 2) xp = &g_fine[(1 * 32 + sub) * 32];
    // ring guards (deferred, coarse)
    const unsigned* dfp = 0;
    if (stage == 0)      dfp = &g_coarse[(1 * 2 + bhalf) * 32];
    else if (stage == 1) dfp = &g_coarse[(2 * 2 + bhalf) * 32];
    else if (stage == 3) dfp = &g_coarse[(0 * 2 + bhalf) * 32];

    // ---- prestage weights once (bijective rotation swizzle) ----
    const float* Wsrc = (stage == 0) ? Whh0 : (stage == 1) ? Wih1
                      : (stage == 2) ? Whh1 : Wih0;
    int K = (stage == 3) ? 256 : 512;
    {
        const float* Wr = Wsrc + (size_t)h0 * K;
        int kshift = (stage == 3) ? 6 : 7;
        int kmask = (K / 4) - 1;
        int nld = (stage == 3) ? 4 : 8;
        for (int r = 0; r < nld; r++) {
            int idx = tid + r * 512;
            int row = idx >> kshift, k4 = idx & kmask;
            float4 v = __ldg((const float4*)(Wr + (size_t)row * K) + k4);
            int rp = row >> 1, lo = row & 1;
            int s = (rp >> 1) | ((rp & 1) << 3);
            float vv[4] = {v.x, v.y, v.z, v.w};
            #pragma unroll
            for (int q = 0; q < 4; q++)
                *(float2*)(smb + (k4 * 4 + q) * 256 + s * 16 + lo * 8) =
                    make_float2(vv[q], vv[q]);
        }
    }
    unsigned smem_u = (unsigned)__cvta_generic_to_shared(smb);
    unsigned s1off = (unsigned)(rg * 16);
    unsigned s2off = (unsigned)((8 + rg) * 16);
    int nkw = (stage == 3) ? 16 : 32;   // k per warp
    unsigned wseg0 = smem_u + (unsigned)(ks * nkw) * 256;
    unsigned hseg0 = smem_u + HB + (unsigned)(ks * nkw) * 128 + (unsigned)(bg * 32);

    int o = tid;
    int orow = o >> 4, obp = o & 15;
    int hg = h0 + orow;
    float bias = 0.0f;
    if (stage == 1) bias = __ldg(bih1 + hg) + __ldg(bhh1 + hg);
    if (stage == 3) bias = __ldg(bih0 + hg) + __ldg(bhh0 + hg);
    unsigned rbase = smem_u + HB +
        (unsigned)(((o >> 4) * 16 + (((o & 15) + (o >> 6)) & 15)) * 8);

    __syncthreads();

    for (int i = 0; i < NITER; i++) {
        bool active = (stage == 0) ? (i < T)
                    : (stage == 1) ? (i >= 1 && i <= T)
                    : (stage == 2) ? (i >= 2)
                                   : (i < T);
        if (active) {
            int t = i - ((stage == 1) ? 1 : (stage == 2) ? 2 : 0);

            if (stage != 3) {
                // ---- per-warp: poll own chunk producer (+ ex producer) ----
                if (lane == 0) poll_ge(wp, (unsigned)i);
                else if (lane == 1 && xp)
                    poll_ge(xp, (unsigned)(stage == 0 ? i + 1 : i));
                __syncwarp();

                // ---- per-warp chunk staging: 32 k x 128B (warp-private) ----
                const float* src = (stage == 0) ? g_h1T[(t - 1) & 3]
                                 : (stage == 1) ? g_h1T[t & 3]
                                                : g_h2T[(t - 1) & 3];
                const float4* s4 = (const float4*)src;
                float4 pf[8];
                #pragma unroll
                for (int r = 0; r < 8; r++) {
                    int m = ks * 256 + lane + r * 32;
                    pf[r] = __ldcg(s4 + (m >> 3) * 16 + bhalf * 8 + (m & 7));
                }
                #pragma unroll
                for (int r = 0; r < 8; r++) {
                    int m = ks * 256 + lane + r * 32;
                    *(float4*)(smb + HB + (m >> 3) * 128 + (m & 7) * 16) = pf[r];
                }
                __syncwarp();
            } else {
                // stage 3: block-wide x transpose staging (free-running)
                #pragma unroll
                for (int r = 0; r < 4; r++) {
                    int f = tid + r * 512;
                    int bl = f >> 6, d4 = f & 63;
                    float4 v = __ldg((const float4*)(x +
                        ((size_t)(bhalf * 32 + bl) * T + t) * 256) + d4);
                    *(float4*)(smb + XI + bl * 1040 + d4 * 16) = v;
                }
                __syncthreads();
                #pragma unroll
                for (int r = 0; r < 4; r++) {
                    int m = tid + r * 512;
                    int k = m >> 3, c = m & 7;
                    float4 g;
                    g.x = *(float*)(smb + XI + (4 * c + 0) * 1040 + k * 4);
                    g.y = *(float*)(smb + XI + (4 * c + 1) * 1040 + k * 4);
                    g.z = *(float*)(smb + XI + (4 * c + 2) * 1040 + k * 4);
                    g.w = *(float*)(smb + XI + (4 * c + 3) * 1040 + k * 4);
                    *(float4*)(smb + HB + k * 128 + c * 16) = g;
                }
                __syncthreads();
            }

            // ex load (producers gated by per-warp xp poll above)
            float2 ex;
            if (stage == 0)
                ex = __ldcg((const float2*)(g_xw0R[i & 7] + hg * B + bhalf * 32) + obp);
            else if (stage == 2)
                ex = __ldcg((const float2*)(g_zT[t & 3] + hg * B + bhalf * 32) + obp);
            else
                ex = make_float2(bias, bias);

            // ---- body: nkw k x (4 one-phase LDS.128 + 16 FFMA2), warp-local ----
            unsigned long long acc[16];
            #pragma unroll
            for (int j = 0; j < 16; j++) acc[j] = 0;
            unsigned wa = wseg0, ha = hseg0;
            #pragma unroll 8
            for (int kk = 0; kk < nkw; kk++) {
                unsigned long long w0, w1, w2, w3, hA, hB2, hC, hD;
                lds_v2u64(wa + s1off, w0, w1);
                lds_v2u64(wa + s2off, w2, w3);
                lds_v2u64(ha, hA, hB2);
                lds_v2u64(ha + 16, hC, hD);
                FMA2(acc[0],  w0, hA); FMA2(acc[1],  w0, hB2);
                FMA2(acc[2],  w0, hC); FMA2(acc[3],  w0, hD);
                FMA2(acc[4],  w1, hA); FMA2(acc[5],  w1, hB2);
                FMA2(acc[6],  w1, hC); FMA2(acc[7],  w1, hD);
                FMA2(acc[8],  w2, hA); FMA2(acc[9],  w2, hB2);
                FMA2(acc[10], w2, hC); FMA2(acc[11], w2, hD);
                FMA2(acc[12], w3, hA); FMA2(acc[13], w3, hB2);
                FMA2(acc[14], w3, hC); FMA2(acc[15], w3, hD);
                wa += 256; ha += 128;
            }
            __syncwarp();   // warp's hseg reads done -> its own partial region (same 4KB)

            // ---- partials (each warp writes ONLY its own aliased 4KB region) ----
            #pragma unroll
            for (int r = 0; r < 4; r++) {
                #pragma unroll
                for (int p = 0; p < 4; p++) {
                    int oo = (rg * 4 + r) * 16 + bg * 4 + p;
                    unsigned a = smem_u + HB + (unsigned)(ks * 4096 +
                        ((oo >> 4) * 16 + (((oo & 15) + (oo >> 6)) & 15)) * 8);
                    sts_u64(a, acc[r * 4 + p]);
                }
            }
            // deferred ring-guard poll (coarse counters; overlaps partial stores)
            if (tid == 64 && dfp) {
                unsigned tD = (stage == 3) ? ((i >= 8) ? 16u * (i - 7) : 0u)
                                           : ((i >= 2) ? 16u * (i - 2) : 0u);
                poll_ge(dfp, tD);
            }
            __syncthreads();

            // ---- reduce 16 partials for output o ----
            unsigned long long sa = 0, sb = 0;
            #pragma unroll
            for (int j = 0; j < 16; j += 2) {
                unsigned long long q0, q1;
                lds_u64(rbase + (unsigned)(j * 4096), q0);
                lds_u64(rbase + (unsigned)((j + 1) * 4096), q1);
                sa = add2(sa, q0);
                sb = add2(sb, q1);
            }
            float2 f = unpack2(add2(sa, sb));
            f.x += ex.x; f.y += ex.y;
            if (stage == 0 || stage == 2) { f.x = tanh_fast(f.x); f.y = tanh_fast(f.y); }
            float* dst = (stage == 0) ? g_h1T[t & 3]
                       : (stage == 1) ? g_zT[t & 3]
                       : (stage == 2) ? g_h2T[t & 3]
                                      : g_xw0R[t & 7];
            __stcg((float2*)(dst + hg * B + bhalf * 32) + obp, f);
        }
        // ---- arrive: fine (data-ready) + coarse (ring guards) ----
        __syncthreads();
        if (tid == 0)
            asm volatile("red.release.gpu.global.add.u32 [%0], %1;"
                         :: "l"(fine_own), "r"(1u) : "memory");
        else if (tid == 32)
            asm volatile("red.release.gpu.global.add.u32 [%0], %1;"
                         :: "l"(coarse_own), "r"(1u) : "memory");
    }
}

__global__ void k_fc(const float* __restrict__ fcw, const float* __restrict__ fcb,
                     float* __restrict__ out) {
    __shared__ float logits[64][2];
    int tid = threadIdx.x;
    int b = tid >> 1, c = tid & 1;
    const float* h2 = g_h2T[(T - 1) & 3];
    float acc = __ldg(fcb + c);
    for (int k = 0; k < 512; k++)
        acc = fmaf(h2[k * 64 + b], __ldg(fcw + c * 512 + k), acc);
    logits[b][c] = acc;
    __syncthreads();
    if (c == 0) {
        float l0 = logits[b][0], l1 = logits[b][1];
        float m = fmaxf(l0, l1);
        float e0 = expf(l0 - m), e1 = expf(l1 - m);
        float s = e0 + e1;
        out[b * 2 + 0] = e0 / s;
        out[b * 2 + 1] = e1 / s;
    }
}

extern "C" void kernel_launch(void* const* d_in, const int* in_sizes, int n_in,
                              void* d_out, int out_size) {
    const float* x    = (const float*)d_in[0];
    const float* Wih0 = (const float*)d_in[1];
    const float* Whh0 = (const float*)d_in[2];
    const float* bih0 = (const float*)d_in[3];
    const float* bhh0 = (const float*)d_in[4];
    const float* Wih1 = (const float*)d_in[5];
    const float* Whh1 = (const float*)d_in[6];
    const float* bih1 = (const float*)d_in[7];
    const float* bhh1 = (const float*)d_in[8];
    const float* fcw  = (const float*)d_in[9];
    const float* fcb  = (const float*)d_in[10];
    float* out = (float*)d_out;

    cudaFuncSetAttribute(k_recur, cudaFuncAttributeMaxDynamicSharedMemorySize, 196608);

    k_zero<<<512, 256>>>();
    k_recur<<<128, 512, 196608>>>(Whh0, Wih1, Whh1, Wih0, x,
                                  bih0, bhh0, bih1, bhh1);
    k_fc<<<1, 128>>>(fcw, fcb, out);
}

// round 15
// speedup vs baseline: 1.3426x; 1.3426x over previous
#include <cuda_runtime.h>
#include <math.h>

#define T 2048
#define B 64
#define H 512
#define D 256
#define NITER (T + 2)

__device__ float g_xw0R[8][H * B];   // xw0 ring (L2-resident, 1MB)
__device__ float g_h1T[4][H * B];    // rings, slot = t & 3
__device__ float g_h2T[4][H * B];
__device__ float g_zT[4][H * B];
__device__ unsigned g_arr[4 * 32];   // per-group monotonic arrival counters (128B apart)

__device__ __forceinline__ void lds_v2u64(unsigned addr, unsigned long long& a,
                                          unsigned long long& b) {
    asm volatile("ld.shared.v2.u64 {%0,%1}, [%2];" : "=l"(a), "=l"(b) : "r"(addr));
}
__device__ __forceinline__ void lds_u64(unsigned addr, unsigned long long& a) {
    asm volatile("ld.shared.u64 %0, [%1];" : "=l"(a) : "r"(addr));
}
__device__ __forceinline__ void sts_u64(unsigned addr, unsigned long long v) {
    asm volatile("st.shared.u64 [%0], %1;" :: "r"(addr), "l"(v));
}
#define FMA2(acc, w, h) \
    asm("fma.rn.f32x2 %0, %1, %2, %0;" : "+l"(acc) : "l"(w), "l"(h))
__device__ __forceinline__ unsigned long long add2(unsigned long long a,
                                                   unsigned long long b) {
    unsigned long long d;
    asm("add.rn.f32x2 %0, %1, %2;" : "=l"(d) : "l"(a), "l"(b));
    return d;
}
__device__ __forceinline__ float2 unpack2(unsigned long long v) {
    float2 r;
    asm("mov.b64 {%0,%1}, %2;" : "=f"(r.x), "=f"(r.y) : "l"(v));
    return r;
}
__device__ __forceinline__ float tanh_fast(float v) {
    asm("tanh.approx.f32 %0, %0;" : "+f"(v));
    return v;
}
__device__ __forceinline__ void poll_ge(const unsigned* p, unsigned target) {
    unsigned c;
    do {
        asm volatile("ld.global.acquire.gpu.u32 %0, [%1];" : "=r"(c) : "l"(p) : "memory");
    } while ((int)(c - target) < 0);
}

// ---- zero recurrent state rings AND counters (every launch/replay) ----
__global__ void k_zero() {
    int idx = blockIdx.x * 256 + threadIdx.x;
    if (idx < 4 * H * B) {
        ((float*)g_h1T)[idx] = 0.0f;
        ((float*)g_h2T)[idx] = 0.0f;
    }
    if (blockIdx.x == 0 && threadIdx.x < 4) g_arr[threadIdx.x * 32] = 0u;
}

// ---- persistent decoupled 4-group pipeline (R12 sync structure) ----
// grp 0 (blk  0- 31): h1[t]=tanh(xw0[t] + Whh0 h1[t-1]),  t=i,   K=512
// grp 1 (blk 32- 63): z[t]=bias1 + Wih1 h1[t],            t=i-1, K=512
// grp 2 (blk 64- 95): h2[t]=tanh(z[t] + Whh1 h2[t-1]),    t=i-2, K=512
// grp 3 (blk 96-127): xw0[t]=bias0 + Wih0 x[t],           t=i,   K=256 (free-runs)
// NEW vs R12: stages 0-2 stage their h chunk WARP-LOCALLY (warp ks loads/stores
// exactly hbuf chunk [32ks,32ks+32), which also equals its partials region), so
// staging->body->partials need only __syncwarp: 2 block syncs removed per iter.
__global__ void __launch_bounds__(512, 1) k_recur(
    const float* __restrict__ Whh0, const float* __restrict__ Wih1,
    const float* __restrict__ Whh1, const float* __restrict__ Wih0,
    const float* __restrict__ x,
    const float* __restrict__ bih0, const float* __restrict__ bhh0,
    const float* __restrict__ bih1, const float* __restrict__ bhh1)
{
    extern __shared__ char smb[];
    const unsigned HB = 131072u;
    const unsigned XI = 65536u;      // x intermediate tile (stage 3 only)

    int stage = blockIdx.x >> 5;
    int sub = blockIdx.x & 31;
    int rowblk = sub >> 1, bhalf = sub & 1;
    int h0 = rowblk * 32;
    int tid = threadIdx.x;
    int ks = tid >> 5;
    int lane = tid & 31;
    int rg = lane >> 2, bg = lane & 3;

    // ---- prestage weights once (bijective rotation swizzle) ----
    const float* Wsrc = (stage == 0) ? Whh0 : (stage == 1) ? Wih1
                      : (stage == 2) ? Whh1 : Wih0;
    int K = (stage == 3) ? 256 : 512;
    {
        const float* Wr = Wsrc + (size_t)h0 * K;
        int kshift = (stage == 3) ? 6 : 7;
        int kmask = (K / 4) - 1;
        int nld = (stage == 3) ? 4 : 8;
        for (int r = 0; r < nld; r++) {
            int idx = tid + r * 512;
            int row = idx >> kshift, k4 = idx & kmask;
            float4 v = __ldg((const float4*)(Wr + (size_t)row * K) + k4);
            int rp = row >> 1, lo = row & 1;
            int s = (rp >> 1) | ((rp & 1) << 3);
            float vv[4] = {v.x, v.y, v.z, v.w};
            #pragma unroll
            for (int q = 0; q < 4; q++)
                *(float2*)(smb + (k4 * 4 + q) * 256 + s * 16 + lo * 8) =
                    make_float2(vv[q], vv[q]);
        }
    }
    unsigned smem_u = (unsigned)__cvta_generic_to_shared(smb);
    unsigned s1off = (unsigned)(rg * 16);
    unsigned s2off = (unsigned)((8 + rg) * 16);
    int nkw = (stage == 3) ? 16 : 32;   // k per warp
    unsigned wseg0 = smem_u + (unsigned)(ks * nkw) * 256;
    unsigned hseg0 = smem_u + HB + (unsigned)(ks * nkw) * 128 + (unsigned)(bg * 32);

    int o = tid;
    int orow = o >> 4, obp = o & 15;
    int hg = h0 + orow;
    float bias = 0.0f;
    if (stage == 1) bias = __ldg(bih1 + hg) + __ldg(bhh1 + hg);
    if (stage == 3) bias = __ldg(bih0 + hg) + __ldg(bhh0 + hg);
    unsigned rbase = smem_u + HB +
        (unsigned)(((o >> 4) * 16 + (((o & 15) + (o >> 6)) & 15)) * 8);

    __syncthreads();

    for (int i = 0; i < NITER; i++) {
        // ---- upfront waits (R12 structure: 2 pollers, coarse counters) ----
        const unsigned *upA = 0, *upB = 0, *dfp = 0;
        unsigned tA = 0, tB = 0, tD = 0;
        if (stage == 0) {
            upA = &g_arr[0];  tA = 32u * i;                 // own h1 recurrence
            upB = &g_arr[96]; tB = 32u * (i + 1);           // xw0[i] ready
            dfp = &g_arr[32]; tD = (i >= 2) ? 32u * (i - 2) : 0u;  // h1 ring guard
        } else if (stage == 1) {
            upA = &g_arr[0];  tA = 32u * i;                 // h1[i-1] ready
            dfp = &g_arr[64]; tD = (i >= 2) ? 32u * (i - 2) : 0u;  // z ring guard
        } else if (stage == 2) {
            upA = &g_arr[64]; tA = 32u * i;                 // own h2 recurrence
            upB = &g_arr[32]; tB = 32u * i;                 // z[i-2] ready
        } else {
            dfp = &g_arr[0];  tD = (i >= 8) ? 32u * (i - 7) : 0u;  // xw0 ring guard
        }
        if (tid == 0 && upA) poll_ge(upA, tA);
        else if (tid == 32 && upB) poll_ge(upB, tB);
        __syncthreads();

        bool active = (stage == 0) ? (i < T)
                    : (stage == 1) ? (i >= 1 && i <= T)
                    : (stage == 2) ? (i >= 2)
                                   : (i < T);
        if (active) {
            int t = i - ((stage == 1) ? 1 : (stage == 2) ? 2 : 0);

            if (stage != 3) {
                // ---- WARP-LOCAL chunk staging: warp ks loads/stores its own
                //      hbuf chunk [32ks, 32ks+32) (4KB). Coalesced: 8 lanes
                //      read 128B contiguous per k-row. ----
                const float* src = (stage == 0) ? g_h1T[(t - 1) & 3]
                                 : (stage == 1) ? g_h1T[t & 3]
                                                : g_h2T[(t - 1) & 3];
                const float4* s4 = (const float4*)src;
                float4 pf[8];
                #pragma unroll
                for (int r = 0; r < 8; r++) {
                    int m = ks * 256 + lane + r * 32;
                    pf[r] = __ldcg(s4 + (m >> 3) * 16 + bhalf * 8 + (m & 7));
                }
                #pragma unroll
                for (int r = 0; r < 8; r++) {
                    int m = ks * 256 + lane + r * 32;
                    *(float4*)(smb + HB + (m >> 3) * 128 + (m & 7) * 16) = pf[r];
                }
                __syncwarp();
            } else {
                // stage 3: block-wide x transpose staging (needs block syncs)
                #pragma unroll
                for (int r = 0; r < 4; r++) {
                    int f = tid + r * 512;
                    int bl = f >> 6, d4 = f & 63;
                    float4 v = __ldg((const float4*)(x +
                        ((size_t)(bhalf * 32 + bl) * T + t) * 256) + d4);
                    *(float4*)(smb + XI + bl * 1040 + d4 * 16) = v;
                }
                __syncthreads();
                #pragma unroll
                for (int r = 0; r < 4; r++) {
                    int m = tid + r * 512;
                    int k = m >> 3, c = m & 7;
                    float4 g;
                    g.x = *(float*)(smb + XI + (4 * c + 0) * 1040 + k * 4);
                    g.y = *(float*)(smb + XI + (4 * c + 1) * 1040 + k * 4);
                    g.z = *(float*)(smb + XI + (4 * c + 2) * 1040 + k * 4);
                    g.w = *(float*)(smb + XI + (4 * c + 3) * 1040 + k * 4);
                    *(float4*)(smb + HB + k * 128 + c * 16) = g;
                }
                __syncthreads();
            }

            // ex load (gated by the block-level poll + sync at loop top)
            float2 ex;
            if (stage == 0)
                ex = __ldcg((const float2*)(g_xw0R[i & 7] + hg * B + bhalf * 32) + obp);
            else if (stage == 2)
                ex = __ldcg((const float2*)(g_zT[t & 3] + hg * B + bhalf * 32) + obp);
            else
                ex = make_float2(bias, bias);

            // ---- body: nkw k x (4 one-phase LDS.128 + 16 FFMA2), warp-local ----
            unsigned long long acc[16];
            #pragma unroll
            for (int j = 0; j < 16; j++) acc[j] = 0;
            unsigned wa = wseg0, ha = hseg0;
            #pragma unroll 8
            for (int kk = 0; kk < nkw; kk++) {
                unsigned long long w0, w1, w2, w3, hA, hB2, hC, hD;
                lds_v2u64(wa + s1off, w0, w1);
                lds_v2u64(wa + s2off, w2, w3);
                lds_v2u64(ha, hA, hB2);
                lds_v2u64(ha + 16, hC, hD);
                FMA2(acc[0],  w0, hA); FMA2(acc[1],  w0, hB2);
                FMA2(acc[2],  w0, hC); FMA2(acc[3],  w0, hD);
                FMA2(acc[4],  w1, hA); FMA2(acc[5],  w1, hB2);
                FMA2(acc[6],  w1, hC); FMA2(acc[7],  w1, hD);
                FMA2(acc[8],  w2, hA); FMA2(acc[9],  w2, hB2);
                FMA2(acc[10], w2, hC); FMA2(acc[11], w2, hD);
                FMA2(acc[12], w3, hA); FMA2(acc[13], w3, hB2);
                FMA2(acc[14], w3, hC); FMA2(acc[15], w3, hD);
                wa += 256; ha += 128;
            }
            // stages 0-2: warp's partials region == its own hbuf chunk -> syncwarp
            // stage 3:    partials (64KB) overlap other warps' hbuf -> block sync
            if (stage == 3) __syncthreads();
            else __syncwarp();

            // ---- partials (each warp writes only its own aliased 4KB region) ----
            #pragma unroll
            for (int r = 0; r < 4; r++) {
                #pragma unroll
                for (int p = 0; p < 4; p++) {
                    int oo = (rg * 4 + r) * 16 + bg * 4 + p;
                    unsigned a = smem_u + HB + (unsigned)(ks * 4096 +
                        ((oo >> 4) * 16 + (((oo & 15) + (oo >> 6)) & 15)) * 8);
                    sts_u64(a, acc[r * 4 + p]);
                }
            }
            // deferred ring-guard poll (overlaps partial stores)
            if (tid == 64 && dfp) poll_ge(dfp, tD);
            __syncthreads();

            // ---- reduce 16 partials for output o ----
            unsigned long long sa = 0, sb = 0;
            #pragma unroll
            for (int j = 0; j < 16; j += 2) {
                unsigned long long q0, q1;
                lds_u64(rbase + (unsigned)(j * 4096), q0);
                lds_u64(rbase + (unsigned)((j + 1) * 4096), q1);
                sa = add2(sa, q0);
                sb = add2(sb, q1);
            }
            float2 f = unpack2(add2(sa, sb));
            f.x += ex.x; f.y += ex.y;
            if (stage == 0 || stage == 2) { f.x = tanh_fast(f.x); f.y = tanh_fast(f.y); }
            float* dst = (stage == 0) ? g_h1T[t & 3]
                       : (stage == 1) ? g_zT[t & 3]
                       : (stage == 2) ? g_h2T[t & 3]
                                      : g_xw0R[t & 7];
            __stcg((float2*)(dst + hg * B + bhalf * 32) + obp, f);
        }
        // ---- arrive (trailing barrier merged into next iter's top barrier) ----
        __syncthreads();
        if (tid == 0)
            asm volatile("red.release.gpu.global.add.u32 [%0], %1;"
                         :: "l"(&g_arr[stage * 32]), "r"(1u) : "memory");
    }
}

__global__ void k_fc(const float* __restrict__ fcw, const float* __restrict__ fcb,
                     float* __restrict__ out) {
    __shared__ float logits[64][2];
    int tid = threadIdx.x;
    int b = tid >> 1, c = tid & 1;
    const float* h2 = g_h2T[(T - 1) & 3];
    float acc = __ldg(fcb + c);
    for (int k = 0; k < 512; k++)
        acc = fmaf(h2[k * 64 + b], __ldg(fcw + c * 512 + k), acc);
    logits[b][c] = acc;
    __syncthreads();
    if (c == 0) {
        float l0 = logits[b][0], l1 = logits[b][1];
        float m = fmaxf(l0, l1);
        float e0 = expf(l0 - m), e1 = expf(l1 - m);
        float s = e0 + e1;
        out[b * 2 + 0] = e0 / s;
        out[b * 2 + 1] = e1 / s;
    }
}

extern "C" void kernel_launch(void* const* d_in, const int* in_sizes, int n_in,
                              void* d_out, int out_size) {
    const float* x    = (const float*)d_in[0];
    const float* Wih0 = (const float*)d_in[1];
    const float* Whh0 = (const float*)d_in[2];
    const float* bih0 = (const float*)d_in[3];
    const float* bhh0 = (const float*)d_in[4];
    const float* Wih1 = (const float*)d_in[5];
    const float* Whh1 = (const float*)d_in[6];
    const float* bih1 = (const float*)d_in[7];
    const float* bhh1 = (const float*)d_in[8];
    const float* fcw  = (const float*)d_in[9];
    const float* fcb  = (const float*)d_in[10];
    float* out = (float*)d_out;

    cudaFuncSetAttribute(k_recur, cudaFuncAttributeMaxDynamicSharedMemorySize, 196608);

    k_zero<<<512, 256>>>();
    k_recur<<<128, 512, 196608>>>(Whh0, Wih1, Whh1, Wih0, x,
                                  bih0, bhh0, bih1, bhh1);
    k_fc<<<1, 128>>>(fcw, fcb, out);
}